// round 14
// baseline (speedup 1.0000x reference)
#include <cuda_runtime.h>
#include <math.h>
#include <stdint.h>

// ---------------- problem constants ----------------
#define BB 32
#define NN 1369
#define DD 768
#define KK 12
#define TT 3
#define HH 8
#define HD 96
#define BNROWS (BB * NN)          // 43808
#define SROWS  (BB * KK)          // 384
#define NB 148                    // persistent grid = #SMs
#define NT 512
#define NWARP 16
#define NCH 9
#define CH_TOK 153
#define NUNITS (BB * NCH)         // 288
#define TILE_TOK 24
#define SCALE_QK 0.03608439182435161f
#define SCALE_HD 0.10206207261596575f

// dynamic smem layout (floats)
#define SM_TILE0 0                 // 24*768 = 18432
#define SM_TILE1 18432
#define SM_Q     36864             // 12*768 = 9216
#define SM_AT    46080             // 24*12 = 288
#define SM_MASS  46368             // 16
#define SM_TOTALF 46384
#define SMEM_BYTES (SM_TOTALF * 4)  // 185536 B

// ---------------- scratch (device globals) ----------------
__device__ float g_wkt [DD * DD];
__device__ float g_wqk [DD * DD];
__device__ float g_fn  [(size_t)BNROWS * DD];
__device__ float g_sn  [SROWS * DD];
__device__ float g_q   [SROWS * DD];
__device__ float g_pupd[(size_t)NUNITS * KK * DD];
__device__ float g_pmass[NUNITS * KK];
__device__ float g_ub  [SROWS * DD];
__device__ float g_upd [SROWS * DD];
__device__ float g_h1  [SROWS * DD];
__device__ float g_qkvb[SROWS * 3 * DD];
__device__ float g_ob  [SROWS * DD];
__device__ float g_x1  [SROWS * DD];
__device__ float g_h2  [SROWS * DD];
__device__ float g_g1  [SROWS * 4 * DD];
__device__ float g_x2  [SROWS * DD];
__device__ float g_h3  [SROWS * DD];
__device__ float g_g2  [SROWS * 4 * DD];
__device__ float g_slots[SROWS * DD];

__device__ int g_bar_count = 0;
__device__ int g_bar_gen   = 0;

// ---------------- helpers ----------------
__device__ __forceinline__ float gelu_exact(float x) {
    return 0.5f * x * (1.0f + erff(x * 0.70710678118654752f));
}
__device__ __forceinline__ uint32_t f2tf(float x) {
    uint32_t y;
    asm("cvt.rna.tf32.f32 %0, %1;" : "=r"(y) : "f"(x));
    return y;
}
__device__ __forceinline__ void cp16(void* smem_dst, const void* gmem_src, bool pred) {
    uint32_t s = (uint32_t)__cvta_generic_to_shared(smem_dst);
    int sz = pred ? 16 : 0;
    asm volatile("cp.async.ca.shared.global [%0], [%1], 16, %2;\n"
                 :: "r"(s), "l"(gmem_src), "r"(sz));
}
__device__ __forceinline__ void cp_commit() { asm volatile("cp.async.commit_group;\n"); }
template<int N>
__device__ __forceinline__ void cp_wait_n() { asm volatile("cp.async.wait_group %0;\n" :: "n"(N) : "memory"); }
__device__ __forceinline__ void cp_wait1()  { asm volatile("cp.async.wait_group 1;\n"); }
__device__ __forceinline__ void cp_waitall(){ asm volatile("cp.async.wait_all;\n" ::: "memory"); }

// ---------------- software grid barrier (volatile-load spin) ----------------
__device__ __forceinline__ void gridbar() {
    __syncthreads();
    if (threadIdx.x == 0) {
        __threadfence();
        int gen = *(volatile int*)&g_bar_gen;
        if (atomicAdd(&g_bar_count, 1) == NB - 1) {
            g_bar_count = 0;
            __threadfence();
            atomicAdd(&g_bar_gen, 1);
        } else {
            while (*(volatile int*)&g_bar_gen == gen) { __nanosleep(64); }
        }
        __threadfence();
    }
    __syncthreads();
}

// ---------------- LayerNorm: warp per row, rows spread across blocks first ----------------
__device__ void dev_ln(const float* __restrict__ x, const float* __restrict__ x2,
                       const float* __restrict__ gam, const float* __restrict__ bet,
                       float* __restrict__ out, int rows) {
    int warp = threadIdx.x >> 5, lane = threadIdx.x & 31;
    for (int r = blockIdx.x + NB * warp; r < rows; r += NB * NWARP) {
        const float4* xr = (const float4*)(x + (size_t)r * DD);
        const float4* x2r = x2 ? (const float4*)(x2 + (size_t)r * DD) : nullptr;
        float4 v[6];
        float s = 0.f;
#pragma unroll
        for (int i = 0; i < 6; i++) {
            int d4 = lane + i * 32;
            float4 t = xr[d4];
            if (x2r) { float4 u = x2r[d4]; t.x += u.x; t.y += u.y; t.z += u.z; t.w += u.w; }
            v[i] = t;
            s += t.x + t.y + t.z + t.w;
        }
#pragma unroll
        for (int off = 16; off; off >>= 1) s += __shfl_xor_sync(0xffffffffu, s, off);
        float mean = s * (1.0f / DD);
        float s2 = 0.f;
#pragma unroll
        for (int i = 0; i < 6; i++) {
            float dx = v[i].x - mean, dy = v[i].y - mean, dz = v[i].z - mean, dw = v[i].w - mean;
            s2 += dx * dx + dy * dy + dz * dz + dw * dw;
        }
#pragma unroll
        for (int off = 16; off; off >>= 1) s2 += __shfl_xor_sync(0xffffffffu, s2, off);
        float inv = rsqrtf(s2 * (1.0f / DD) + 1e-5f);
        float4* o4 = (float4*)(out + (size_t)r * DD);
#pragma unroll
        for (int i = 0; i < 6; i++) {
            int d4 = lane + i * 32;
            float4 gv = ((const float4*)gam)[d4];
            float4 bv = ((const float4*)bet)[d4];
            float4 t;
            t.x = (v[i].x - mean) * inv * gv.x + bv.x;
            t.y = (v[i].y - mean) * inv * gv.y + bv.y;
            t.z = (v[i].z - mean) * inv * gv.z + bv.z;
            t.w = (v[i].w - mean) * inv * gv.w + bv.w;
            o4[d4] = t;
        }
    }
}

// ---------------- TF32 GEMM: 32xTILEN tiles, 16 warps, BK configurable ----------------
template<int TILEN, int BKT>
__device__ void dev_gemm_t(const float* __restrict__ A, const float* __restrict__ W,
                           const float* __restrict__ bias, const float* __restrict__ addsrc,
                           float* __restrict__ C, int M, int Nc, int Kc, int act,
                           float* s_u) {
    constexpr int ASTR = BKT + 4;
    constexpr int ABUF = 32 * ASTR;
    constexpr int ACH  = BKT / 4;
    constexpr int ATOT = 32 * ACH;
    constexpr int BSTR = TILEN + 8;
    constexpr int BBUF = BKT * BSTR;
    constexpr int BCH  = TILEN / 4;
    constexpr int BTOT = BKT * BCH;
    constexpr int TN   = TILEN / 64;
    constexpr int NKS  = BKT / 8;
    float* As = s_u;                          // 2 * ABUF
    float* Bs = s_u + 2 * ABUF;               // 2 * BBUF
    int tid = threadIdx.x, lane = tid & 31, warp = tid >> 5;
    int warp_m = warp >> 3, warp_n = warp & 7;
    int g = lane >> 2, tg = lane & 3;
    int ntn = Nc / TILEN, ntm = (M + 31) >> 5;
    int nkt = Kc / BKT;

    for (int tix = blockIdx.x; tix < ntm * ntn; tix += NB) {
        int bm = (tix / ntn) << 5, bn = (tix % ntn) * TILEN;
        float acc[TN][4];
#pragma unroll
        for (int i = 0; i < TN; i++)
#pragma unroll
            for (int j = 0; j < 4; j++) acc[i][j] = 0.f;

        __syncthreads();
#pragma unroll
        for (int i = 0; i < (ATOT + NT - 1) / NT; i++) {
            int idx = tid + i * NT;
            if (idx < ATOT) {
                int row = idx / ACH, c4 = idx % ACH;
                cp16(&As[row * ASTR + c4 * 4], A + (size_t)(bm + row) * Kc + c4 * 4, (bm + row) < M);
            }
        }
#pragma unroll
        for (int i = 0; i < BTOT / NT; i++) {
            int idx = tid + i * NT;
            int row = idx / BCH, c4 = idx % BCH;
            cp16(&Bs[row * BSTR + c4 * 4], W + (size_t)row * Nc + bn + c4 * 4, true);
        }
        cp_commit();

        for (int t = 0; t < nkt; t++) {
            if (t + 1 < nkt) {
                int k0 = (t + 1) * BKT;
                int buf = (t + 1) & 1;
#pragma unroll
                for (int i = 0; i < (ATOT + NT - 1) / NT; i++) {
                    int idx = tid + i * NT;
                    if (idx < ATOT) {
                        int row = idx / ACH, c4 = idx % ACH;
                        cp16(&As[buf * ABUF + row * ASTR + c4 * 4],
                             A + (size_t)(bm + row) * Kc + k0 + c4 * 4, (bm + row) < M);
                    }
                }
#pragma unroll
                for (int i = 0; i < BTOT / NT; i++) {
                    int idx = tid + i * NT;
                    int row = idx / BCH, c4 = idx % BCH;
                    cp16(&Bs[buf * BBUF + row * BSTR + c4 * 4],
                         W + (size_t)(k0 + row) * Nc + bn + c4 * 4, true);
                }
            }
            cp_commit();
            cp_wait1();
            __syncthreads();
            const float* as = As + (t & 1) * ABUF;
            const float* bs = Bs + (t & 1) * BBUF;
#pragma unroll
            for (int ks = 0; ks < NKS; ks++) {
                int k0 = ks * 8;
                int rb = warp_m * 16;
                uint32_t af[4];
                af[0] = f2tf(as[(rb + g)     * ASTR + k0 + tg]);
                af[1] = f2tf(as[(rb + g + 8) * ASTR + k0 + tg]);
                af[2] = f2tf(as[(rb + g)     * ASTR + k0 + tg + 4]);
                af[3] = f2tf(as[(rb + g + 8) * ASTR + k0 + tg + 4]);
#pragma unroll
                for (int tn = 0; tn < TN; tn++) {
                    int cb = warp_n * (TILEN / 8) + tn * 8;
                    uint32_t bf0 = f2tf(bs[(k0 + tg)     * BSTR + cb + g]);
                    uint32_t bf1 = f2tf(bs[(k0 + tg + 4) * BSTR + cb + g]);
                    asm volatile(
                        "mma.sync.aligned.m16n8k8.row.col.f32.tf32.tf32.f32 "
                        "{%0,%1,%2,%3}, {%4,%5,%6,%7}, {%8,%9}, {%0,%1,%2,%3};\n"
                        : "+f"(acc[tn][0]), "+f"(acc[tn][1]),
                          "+f"(acc[tn][2]), "+f"(acc[tn][3])
                        : "r"(af[0]), "r"(af[1]), "r"(af[2]), "r"(af[3]),
                          "r"(bf0), "r"(bf1));
                }
            }
            __syncthreads();
        }
        cp_waitall();

        int r0 = bm + warp_m * 16 + g;
#pragma unroll
        for (int tn = 0; tn < TN; tn++) {
            int c0 = bn + warp_n * (TILEN / 8) + tn * 8 + tg * 2;
#pragma unroll
            for (int half = 0; half < 2; half++) {
                int rr = r0 + half * 8;
                if (rr >= M) continue;
                float v0 = acc[tn][half * 2 + 0];
                float v1 = acc[tn][half * 2 + 1];
                if (bias) { v0 += bias[c0]; v1 += bias[c0 + 1]; }
                if (act == 1) { v0 = gelu_exact(v0); v1 = gelu_exact(v1); }
                if (addsrc) {
                    v0 += addsrc[(size_t)rr * Nc + c0];
                    v1 += addsrc[(size_t)rr * Nc + c0 + 1];
                }
                C[(size_t)rr * Nc + c0]     = v0;
                C[(size_t)rr * Nc + c0 + 1] = v1;
            }
        }
    }
    __syncthreads();
}

__device__ __forceinline__ void dev_gemm(const float* A, const float* W,
                                         const float* bias, const float* addsrc,
                                         float* C, int M, int Nc, int Kc, int act,
                                         float* s_u) {
    if (Nc >= 2304) dev_gemm_t<256, 32>(A, W, bias, addsrc, C, M, Nc, Kc, act, s_u);
    else            dev_gemm_t<64, 64> (A, W, bias, addsrc, C, M, Nc, Kc, act, s_u);
}

// ---------------- fused slot attention (double-buffered fn tiles) ----------------
__device__ void dev_fused(const float* __restrict__ qmat, const float* __restrict__ fn,
                          float* __restrict__ pupd, float* __restrict__ pmass,
                          float* __restrict__ masks, int write_upd, float* s_u) {
    float* s_q    = s_u + SM_Q;
    float* s_at   = s_u + SM_AT;
    float* s_mass = s_u + SM_MASS;
    int tid = threadIdx.x, lane = tid & 31, warp = tid >> 5;
    const float4* qsv = (const float4*)s_q;
    constexpr int TCH = DD / 4;       // 192 f4 chunks per token row
    constexpr int TTOT = TILE_TOK * TCH;  // 4608

    for (int u = blockIdx.x; u < NUNITS; u += NB) {
        int b = u % BB, ch = u / BB;
        int n0 = ch * CH_TOK;
        int n1 = n0 + CH_TOK; if (n1 > NN) n1 = NN;
        int ntile = (n1 - n0 + TILE_TOK - 1) / TILE_TOK;

        __syncthreads();
        {
            const float4* qb4 = (const float4*)(qmat + (size_t)b * KK * DD);
            float4* qd = (float4*)s_q;
            for (int i = tid; i < KK * DD / 4; i += NT) qd[i] = qb4[i];
        }
        if (tid < KK) s_mass[tid] = 0.f;
        float acc[KK][2];
#pragma unroll
        for (int k = 0; k < KK; k++) { acc[k][0] = 0.f; acc[k][1] = 0.f; }
        __syncthreads();

        // stage tile 0
        {
            float* dst = s_u + SM_TILE0;
            const float* srcb = fn + ((size_t)b * NN + n0) * DD;
#pragma unroll
            for (int i = 0; i < TTOT / NT; i++) {
                int idx = tid + i * NT;
                int row = idx / TCH, c4 = idx % TCH;
                cp16(dst + row * DD + c4 * 4, srcb + (size_t)row * DD + c4 * 4,
                     (n0 + row) < n1);
            }
            cp_commit();
        }

        for (int ti = 0; ti < ntile; ti++) {
            int tbase = n0 + ti * TILE_TOK;
            // prefetch tile ti+1 into other buffer
            if (ti + 1 < ntile) {
                int nb2 = n0 + (ti + 1) * TILE_TOK;
                float* dst = s_u + (((ti + 1) & 1) ? SM_TILE1 : SM_TILE0);
                const float* srcb = fn + ((size_t)b * NN + nb2) * DD;
#pragma unroll
                for (int i = 0; i < TTOT / NT; i++) {
                    int idx = tid + i * NT;
                    int row = idx / TCH, c4 = idx % TCH;
                    cp16(dst + row * DD + c4 * 4, srcb + (size_t)row * DD + c4 * 4,
                         (nb2 + row) < n1);
                }
                cp_commit();
                cp_wait_n<1>();
            } else {
                cp_wait_n<0>();
            }
            __syncthreads();
            const float* s_tile = s_u + ((ti & 1) ? SM_TILE1 : SM_TILE0);

            // ---- logits: warps 0..11 handle 2 tokens each ----
            if (warp < TILE_TOK / 2) {
                float p[2][KK];
#pragma unroll
                for (int tk = 0; tk < 2; tk++)
#pragma unroll
                    for (int s = 0; s < KK; s++) p[tk][s] = 0.f;
                const float4* r0 = (const float4*)(s_tile + (warp * 2) * DD);
                const float4* r1 = (const float4*)(s_tile + (warp * 2 + 1) * DD);
#pragma unroll
                for (int it = 0; it < 6; it++) {
                    int d4 = it * 32 + lane;
                    float4 k0 = r0[d4];
                    float4 k1 = r1[d4];
#pragma unroll
                    for (int s = 0; s < KK; s++) {
                        float4 qv = qsv[s * (DD / 4) + d4];
                        p[0][s] = fmaf(k0.x, qv.x, p[0][s]);
                        p[0][s] = fmaf(k0.y, qv.y, p[0][s]);
                        p[0][s] = fmaf(k0.z, qv.z, p[0][s]);
                        p[0][s] = fmaf(k0.w, qv.w, p[0][s]);
                        p[1][s] = fmaf(k1.x, qv.x, p[1][s]);
                        p[1][s] = fmaf(k1.y, qv.y, p[1][s]);
                        p[1][s] = fmaf(k1.z, qv.z, p[1][s]);
                        p[1][s] = fmaf(k1.w, qv.w, p[1][s]);
                    }
                }
#pragma unroll
                for (int tk = 0; tk < 2; tk++)
#pragma unroll
                    for (int s = 0; s < KK; s++)
#pragma unroll
                        for (int off = 16; off; off >>= 1)
                            p[tk][s] += __shfl_xor_sync(0xffffffffu, p[tk][s], off);
#pragma unroll
                for (int tk = 0; tk < 2; tk++) {
                    int ntok = tbase + warp * 2 + tk;
                    bool valid = ntok < n1;
                    float mx = -1e30f;
#pragma unroll
                    for (int s = 0; s < KK; s++) { p[tk][s] *= SCALE_QK; mx = fmaxf(mx, p[tk][s]); }
                    float tot = 0.f;
                    float e[KK];
#pragma unroll
                    for (int s = 0; s < KK; s++) { e[s] = expf(p[tk][s] - mx); tot += e[s]; }
                    float invt = 1.0f / tot;
                    float mine = (valid && lane < KK) ? e[lane] * invt : 0.f;
                    if (lane < KK) {
                        s_at[(warp * 2 + tk) * KK + lane] = mine;
                        if (write_upd) {
                            if (valid) atomicAdd(&s_mass[lane], mine);
                        } else if (valid) {
                            masks[((size_t)b * NN + ntok) * KK + lane] = mine;
                        }
                    }
                }
            }
            __syncthreads();

            // ---- accumulation: attn^T @ fn from smem ----
            if (write_upd) {
                if (tid < 384) {
                    const float2* tp = (const float2*)s_tile;
#pragma unroll 2
                    for (int j = 0; j < TILE_TOK; j++) {
                        float2 f = tp[j * (DD / 2) + tid];
                        const float4* aj = (const float4*)(s_at + j * KK);
                        float4 a0 = aj[0], a1 = aj[1], a2 = aj[2];
                        acc[0][0]  = fmaf(a0.x, f.x, acc[0][0]);  acc[0][1]  = fmaf(a0.x, f.y, acc[0][1]);
                        acc[1][0]  = fmaf(a0.y, f.x, acc[1][0]);  acc[1][1]  = fmaf(a0.y, f.y, acc[1][1]);
                        acc[2][0]  = fmaf(a0.z, f.x, acc[2][0]);  acc[2][1]  = fmaf(a0.z, f.y, acc[2][1]);
                        acc[3][0]  = fmaf(a0.w, f.x, acc[3][0]);  acc[3][1]  = fmaf(a0.w, f.y, acc[3][1]);
                        acc[4][0]  = fmaf(a1.x, f.x, acc[4][0]);  acc[4][1]  = fmaf(a1.x, f.y, acc[4][1]);
                        acc[5][0]  = fmaf(a1.y, f.x, acc[5][0]);  acc[5][1]  = fmaf(a1.y, f.y, acc[5][1]);
                        acc[6][0]  = fmaf(a1.z, f.x, acc[6][0]);  acc[6][1]  = fmaf(a1.z, f.y, acc[6][1]);
                        acc[7][0]  = fmaf(a1.w, f.x, acc[7][0]);  acc[7][1]  = fmaf(a1.w, f.y, acc[7][1]);
                        acc[8][0]  = fmaf(a2.x, f.x, acc[8][0]);  acc[8][1]  = fmaf(a2.x, f.y, acc[8][1]);
                        acc[9][0]  = fmaf(a2.y, f.x, acc[9][0]);  acc[9][1]  = fmaf(a2.y, f.y, acc[9][1]);
                        acc[10][0] = fmaf(a2.z, f.x, acc[10][0]); acc[10][1] = fmaf(a2.z, f.y, acc[10][1]);
                        acc[11][0] = fmaf(a2.w, f.x, acc[11][0]); acc[11][1] = fmaf(a2.w, f.y, acc[11][1]);
                    }
                }
            }
            __syncthreads();
        }
        if (write_upd) {
            if (tid < 384) {
                float* pu = pupd + (size_t)u * KK * DD;
#pragma unroll
                for (int k = 0; k < KK; k++) {
                    pu[k * DD + 2 * tid]     = acc[k][0];
                    pu[k * DD + 2 * tid + 1] = acc[k][1];
                }
            }
            if (tid < KK) pmass[u * KK + tid] = s_mass[tid];
        }
        __syncthreads();
    }
    __syncthreads();
}

// ---------------- reduce partials ----------------
__device__ void dev_reduce(const float* __restrict__ pupd, const float* __restrict__ pmass,
                           float* __restrict__ ub) {
    int tid = threadIdx.x;
    for (int r = blockIdx.x; r < SROWS; r += NB) {
        int b = r / KK, k = r % KK;
        float m = 0.f;
#pragma unroll
        for (int ch = 0; ch < NCH; ch++) m += pmass[(ch * BB + b) * KK + k];
        float inv = 1.0f / fmaxf(m, 1e-8f);
        for (int d = tid; d < DD; d += NT) {
            float s = 0.f;
#pragma unroll
            for (int ch = 0; ch < NCH; ch++)
                s += pupd[(size_t)(ch * BB + b) * KK * DD + k * DD + d];
            ub[(size_t)r * DD + d] = s * inv;
        }
    }
}

// ---------------- tiny multi-head self-attention ----------------
__device__ void dev_blockattn(const float* __restrict__ qkv, float* __restrict__ obuf,
                              float* s_u) {
    float* qs = s_u;
    float* ks = s_u + 1152;
    float* vs = s_u + 2304;
    float* sc = s_u + 3456;
    float* at = s_u + 3600;
    int tid = threadIdx.x;
    for (int u = blockIdx.x; u < BB * HH; u += NB) {
        int b = u >> 3, h = u & 7;
        __syncthreads();
        for (int idx = tid; idx < KK * HD; idx += NT) {
            int r = idx / HD, c = idx % HD;
            size_t base = ((size_t)(b * KK + r)) * (3 * DD) + h * HD + c;
            qs[r * HD + c] = qkv[base];
            ks[r * HD + c] = qkv[base + DD];
            vs[r * HD + c] = qkv[base + 2 * DD];
        }
        __syncthreads();
        if (tid < 144) {
            int i = tid / KK, j = tid % KK;
            float s = 0.f;
#pragma unroll
            for (int d = 0; d < HD; d++) s = fmaf(qs[i * HD + d], ks[j * HD + d], s);
            sc[i * KK + j] = s * SCALE_HD;
        }
        __syncthreads();
        if (tid < 144) {
            int i = tid / KK, j = tid % KK;
            float mx = -1e30f;
#pragma unroll
            for (int jj = 0; jj < KK; jj++) mx = fmaxf(mx, sc[i * KK + jj]);
            float tot = 0.f;
#pragma unroll
            for (int jj = 0; jj < KK; jj++) tot += expf(sc[i * KK + jj] - mx);
            at[i * KK + j] = expf(sc[i * KK + j] - mx) / tot;
        }
        __syncthreads();
        for (int idx = tid; idx < KK * HD; idx += NT) {
            int r = idx / HD, d = idx % HD;
            float s = 0.f;
#pragma unroll
            for (int jj = 0; jj < KK; jj++) s = fmaf(at[r * KK + jj], vs[jj * HD + d], s);
            obuf[((size_t)(b * KK + r)) * DD + h * HD + d] = s;
        }
        __syncthreads();
    }
    __syncthreads();
}

// ---------------- transpose 768x768 ----------------
__device__ void dev_transpose(const float* __restrict__ in, float* __restrict__ out,
                              float* s_u) {
    float* tile = s_u;
    int tx = threadIdx.x & 31, ty = threadIdx.x >> 5;   // 32 x 16
    for (int tix = blockIdx.x; tix < 24 * 24; tix += NB) {
        int bx = (tix % 24) * 32, by = (tix / 24) * 32;
        __syncthreads();
#pragma unroll
        for (int dy = 0; dy < 32; dy += 16)
            tile[(ty + dy) * 33 + tx] = in[(size_t)(by + ty + dy) * DD + bx + tx];
        __syncthreads();
#pragma unroll
        for (int dy = 0; dy < 32; dy += 16)
            out[(size_t)(bx + ty + dy) * DD + by + tx] = tile[tx * 33 + ty + dy];
    }
    __syncthreads();
}

__device__ void dev_copy(float* __restrict__ dst, const float* __restrict__ src, int n4) {
    for (int i = blockIdx.x * NT + threadIdx.x; i < n4; i += NB * NT)
        ((float4*)dst)[i] = ((const float4*)src)[i];
}

// ---------------- the megakernel ----------------
__global__ __launch_bounds__(NT, 1)
void mega_kernel(const float* features, const float* slots_init,
                 const float* nf_g, const float* nf_b,
                 const float* ns_g, const float* ns_b,
                 const float* Wq, const float* Wk, const float* Wv,
                 const float* mg, const float* mb,
                 const float* mW1, const float* mb1,
                 const float* mW2, const float* mb2,
                 const float* b_ln1g, const float* b_ln1b,
                 const float* b_Wqkv, const float* b_bqkv,
                 const float* b_Wo, const float* b_bo,
                 const float* b_ln2g, const float* b_ln2b,
                 const float* b_W1, const float* b_b1,
                 const float* b_W2, const float* b_b2,
                 float* out) {
    extern __shared__ __align__(16) float s_u[];

    dev_transpose(Wk, g_wkt, s_u);
    dev_ln(features, nullptr, nf_g, nf_b, g_fn, BNROWS);
    dev_copy(g_slots, slots_init, SROWS * DD / 4);
    gridbar();
    dev_gemm(Wq, g_wkt, nullptr, nullptr, g_wqk, DD, DD, DD, 0, s_u);
    gridbar();

    for (int t = 0; t < TT; t++) {
        const float* ln1g = b_ln1g + (size_t)t * DD;
        const float* ln1b = b_ln1b + (size_t)t * DD;
        const float* Wqkv = b_Wqkv + (size_t)t * DD * 3 * DD;
        const float* bqkv = b_bqkv + (size_t)t * 3 * DD;
        const float* Wo   = b_Wo   + (size_t)t * DD * DD;
        const float* bo   = b_bo   + (size_t)t * DD;
        const float* ln2g = b_ln2g + (size_t)t * DD;
        const float* ln2b = b_ln2b + (size_t)t * DD;
        const float* W1   = b_W1   + (size_t)t * DD * 4 * DD;
        const float* b1   = b_b1   + (size_t)t * 4 * DD;
        const float* W2   = b_W2   + (size_t)t * 4 * DD * DD;
        const float* b2   = b_b2   + (size_t)t * DD;

        dev_ln(g_slots, nullptr, ns_g, ns_b, g_sn, SROWS);
        gridbar();
        dev_gemm(g_sn, g_wqk, nullptr, nullptr, g_q, SROWS, DD, DD, 0, s_u);
        dev_ln(g_sn, nullptr, ln1g, ln1b, g_h1, SROWS);
        gridbar();
        dev_fused(g_q, g_fn, g_pupd, g_pmass, nullptr, 1, s_u);
        dev_gemm(g_h1, Wqkv, bqkv, nullptr, g_qkvb, SROWS, 3 * DD, DD, 0, s_u);
        gridbar();
        dev_reduce(g_pupd, g_pmass, g_ub);
        dev_blockattn(g_qkvb, g_ob, s_u);
        gridbar();
        dev_gemm(g_ub, Wv, nullptr, nullptr, g_upd, SROWS, DD, DD, 0, s_u);
        dev_gemm(g_ob, Wo, bo, g_sn, g_x1, SROWS, DD, DD, 0, s_u);
        gridbar();
        dev_ln(g_x1, nullptr, ln2g, ln2b, g_h2, SROWS);
        gridbar();
        dev_gemm(g_h2, W1, b1, nullptr, g_g1, SROWS, 4 * DD, DD, 1, s_u);
        gridbar();
        dev_gemm(g_g1, W2, b2, g_x1, g_x2, SROWS, DD, 4 * DD, 0, s_u);
        gridbar();
        dev_ln(g_upd, g_x2, mg, mb, g_h3, SROWS);
        gridbar();
        dev_gemm(g_h3, mW1, mb1, nullptr, g_g2, SROWS, 4 * DD, DD, 1, s_u);
        gridbar();
        dev_gemm(g_g2, mW2, mb2, g_slots, g_slots, SROWS, DD, 4 * DD, 0, s_u);
        gridbar();
    }

    dev_ln(g_slots, nullptr, ns_g, ns_b, g_sn, SROWS);
    gridbar();
    dev_gemm(g_sn, g_wqk, nullptr, nullptr, g_q, SROWS, DD, DD, 0, s_u);
    dev_copy(out, g_slots, SROWS * DD / 4);
    gridbar();
    dev_fused(g_q, g_fn, nullptr, nullptr, out + (size_t)SROWS * DD, 0, s_u);
}

// ---------------- host ----------------
extern "C" void kernel_launch(void* const* d_in, const int* in_sizes, int n_in,
                              void* d_out, int out_size) {
    const float* features  = (const float*)d_in[0];
    const float* slots_init= (const float*)d_in[1];
    const float* nf_g = (const float*)d_in[2];
    const float* nf_b = (const float*)d_in[3];
    const float* ns_g = (const float*)d_in[4];
    const float* ns_b = (const float*)d_in[5];
    const float* Wq   = (const float*)d_in[6];
    const float* Wk   = (const float*)d_in[7];
    const float* Wv   = (const float*)d_in[8];
    const float* mg   = (const float*)d_in[9];
    const float* mb   = (const float*)d_in[10];
    const float* mW1  = (const float*)d_in[11];
    const float* mb1  = (const float*)d_in[12];
    const float* mW2  = (const float*)d_in[13];
    const float* mb2  = (const float*)d_in[14];
    const float* b_ln1g = (const float*)d_in[15];
    const float* b_ln1b = (const float*)d_in[16];
    const float* b_Wqkv = (const float*)d_in[17];
    const float* b_bqkv = (const float*)d_in[18];
    const float* b_Wo   = (const float*)d_in[19];
    const float* b_bo   = (const float*)d_in[20];
    const float* b_ln2g = (const float*)d_in[21];
    const float* b_ln2b = (const float*)d_in[22];
    const float* b_W1   = (const float*)d_in[23];
    const float* b_b1   = (const float*)d_in[24];
    const float* b_W2   = (const float*)d_in[25];
    const float* b_b2   = (const float*)d_in[26];

    static int configured = 0;
    if (!configured) {
        cudaFuncSetAttribute(mega_kernel, cudaFuncAttributeMaxDynamicSharedMemorySize,
                             SMEM_BYTES);
        configured = 1;
    }

    mega_kernel<<<NB, NT, SMEM_BYTES>>>(features, slots_init, nf_g, nf_b, ns_g, ns_b,
                                        Wq, Wk, Wv, mg, mb, mW1, mb1, mW2, mb2,
                                        b_ln1g, b_ln1b, b_Wqkv, b_bqkv, b_Wo, b_bo,
                                        b_ln2g, b_ln2b, b_W1, b_b1, b_W2, b_b2,
                                        (float*)d_out);
}

// round 15
// speedup vs baseline: 1.1326x; 1.1326x over previous
#include <cuda_runtime.h>
#include <math.h>
#include <stdint.h>

// ---------------- problem constants ----------------
#define BB 32
#define NN 1369
#define DD 768
#define KK 12
#define TT 3
#define HH 8
#define HD 96
#define BNROWS (BB * NN)          // 43808
#define SROWS  (BB * KK)          // 384
#define NB 148                    // persistent grid = #SMs
#define NT 512
#define NWARP 16
#define NCH 9
#define CH_TOK 153
#define NUNITS (BB * NCH)         // 288
#define TILE_TOK 32
#define SCALE_QK 0.03608439182435161f
#define SCALE_HD 0.10206207261596575f

// dynamic smem layout (floats)
#define SM_TILE 0                  // 32*768 = 24576
#define SM_Q    24576              // 12*768 = 9216
#define SM_AT   33792              // 32*12 = 384
#define SM_MASS 34176              // 16
#define SM_TOTALF 34192
#define SMEM_BYTES (SM_TOTALF * 4)

// ---------------- scratch (device globals) ----------------
__device__ float g_wkt [DD * DD];
__device__ float g_wqk [DD * DD];
__device__ float g_fn  [(size_t)BNROWS * DD];
__device__ float g_sn  [SROWS * DD];
__device__ float g_q   [SROWS * DD];
__device__ float g_pupd[(size_t)NUNITS * KK * DD];
__device__ float g_pmass[NUNITS * KK];
__device__ float g_ub  [SROWS * DD];
__device__ float g_upd [SROWS * DD];
__device__ float g_h1  [SROWS * DD];
__device__ float g_qkvb[SROWS * 3 * DD];
__device__ float g_ob  [SROWS * DD];
__device__ float g_x1  [SROWS * DD];
__device__ float g_h2  [SROWS * DD];
__device__ float g_g1  [SROWS * 4 * DD];
__device__ float g_x2  [SROWS * DD];
__device__ float g_h3  [SROWS * DD];
__device__ float g_g2  [SROWS * 4 * DD];
__device__ float g_slots[SROWS * DD];

__device__ int g_bar_count = 0;
__device__ int g_bar_gen   = 0;

// ---------------- helpers ----------------
__device__ __forceinline__ float gelu_exact(float x) {
    return 0.5f * x * (1.0f + erff(x * 0.70710678118654752f));
}
__device__ __forceinline__ uint32_t f2tf(float x) {
    uint32_t y;
    asm("cvt.rna.tf32.f32 %0, %1;" : "=r"(y) : "f"(x));
    return y;
}
__device__ __forceinline__ void cp16(void* smem_dst, const void* gmem_src, bool pred) {
    uint32_t s = (uint32_t)__cvta_generic_to_shared(smem_dst);
    int sz = pred ? 16 : 0;
    asm volatile("cp.async.ca.shared.global [%0], [%1], 16, %2;\n"
                 :: "r"(s), "l"(gmem_src), "r"(sz));
}
__device__ __forceinline__ void cp_commit() { asm volatile("cp.async.commit_group;\n"); }
template<int N>
__device__ __forceinline__ void cp_wait_n() { asm volatile("cp.async.wait_group %0;\n" :: "n"(N) : "memory"); }
__device__ __forceinline__ void cp_wait1()  { asm volatile("cp.async.wait_group 1;\n"); }
__device__ __forceinline__ void cp_waitall(){ asm volatile("cp.async.wait_all;\n" ::: "memory"); }

// ---------------- software grid barrier (volatile-load spin) ----------------
__device__ __forceinline__ void gridbar() {
    __syncthreads();
    if (threadIdx.x == 0) {
        __threadfence();
        int gen = *(volatile int*)&g_bar_gen;
        if (atomicAdd(&g_bar_count, 1) == NB - 1) {
            g_bar_count = 0;
            __threadfence();
            atomicAdd(&g_bar_gen, 1);
        } else {
            while (*(volatile int*)&g_bar_gen == gen) { __nanosleep(64); }
        }
        __threadfence();
    }
    __syncthreads();
}

// ---------------- LayerNorm: warp per row, rows spread across blocks first ----------------
__device__ void dev_ln(const float* __restrict__ x, const float* __restrict__ x2,
                       const float* __restrict__ gam, const float* __restrict__ bet,
                       float* __restrict__ out, int rows) {
    int warp = threadIdx.x >> 5, lane = threadIdx.x & 31;
    for (int r = blockIdx.x + NB * warp; r < rows; r += NB * NWARP) {
        const float4* xr = (const float4*)(x + (size_t)r * DD);
        const float4* x2r = x2 ? (const float4*)(x2 + (size_t)r * DD) : nullptr;
        float4 v[6];
        float s = 0.f;
#pragma unroll
        for (int i = 0; i < 6; i++) {
            int d4 = lane + i * 32;
            float4 t = xr[d4];
            if (x2r) { float4 u = x2r[d4]; t.x += u.x; t.y += u.y; t.z += u.z; t.w += u.w; }
            v[i] = t;
            s += t.x + t.y + t.z + t.w;
        }
#pragma unroll
        for (int off = 16; off; off >>= 1) s += __shfl_xor_sync(0xffffffffu, s, off);
        float mean = s * (1.0f / DD);
        float s2 = 0.f;
#pragma unroll
        for (int i = 0; i < 6; i++) {
            float dx = v[i].x - mean, dy = v[i].y - mean, dz = v[i].z - mean, dw = v[i].w - mean;
            s2 += dx * dx + dy * dy + dz * dz + dw * dw;
        }
#pragma unroll
        for (int off = 16; off; off >>= 1) s2 += __shfl_xor_sync(0xffffffffu, s2, off);
        float inv = rsqrtf(s2 * (1.0f / DD) + 1e-5f);
        float4* o4 = (float4*)(out + (size_t)r * DD);
#pragma unroll
        for (int i = 0; i < 6; i++) {
            int d4 = lane + i * 32;
            float4 gv = ((const float4*)gam)[d4];
            float4 bv = ((const float4*)bet)[d4];
            float4 t;
            t.x = (v[i].x - mean) * inv * gv.x + bv.x;
            t.y = (v[i].y - mean) * inv * gv.y + bv.y;
            t.z = (v[i].z - mean) * inv * gv.z + bv.z;
            t.w = (v[i].w - mean) * inv * gv.w + bv.w;
            o4[d4] = t;
        }
    }
}

// ---------------- TF32 GEMM: 32xTILEN tiles, 16 warps, BK templated ----------------
template<int TILEN, int BKT>
__device__ void dev_gemm_t(const float* __restrict__ A, const float* __restrict__ W,
                           const float* __restrict__ bias, const float* __restrict__ addsrc,
                           float* __restrict__ C, int M, int Nc, int Kc, int act,
                           float* s_u) {
    constexpr int ASTR = BKT + 4;
    constexpr int ABUF = 32 * ASTR;
    constexpr int ACH  = BKT / 4;
    constexpr int ATOT = 32 * ACH;
    constexpr int BSTR = TILEN + 8;
    constexpr int BBUF = BKT * BSTR;
    constexpr int BCH  = TILEN / 4;
    constexpr int BTOT = BKT * BCH;
    constexpr int TN   = TILEN / 64;
    constexpr int NKS  = BKT / 8;
    float* As = s_u;
    float* Bs = s_u + 2 * ABUF;
    int tid = threadIdx.x, lane = tid & 31, warp = tid >> 5;
    int warp_m = warp >> 3, warp_n = warp & 7;
    int g = lane >> 2, tg = lane & 3;
    int ntn = Nc / TILEN, ntm = (M + 31) >> 5;
    int nkt = Kc / BKT;

    for (int tix = blockIdx.x; tix < ntm * ntn; tix += NB) {
        int bm = (tix / ntn) << 5, bn = (tix % ntn) * TILEN;
        float acc[TN][4];
#pragma unroll
        for (int i = 0; i < TN; i++)
#pragma unroll
            for (int j = 0; j < 4; j++) acc[i][j] = 0.f;

        __syncthreads();
#pragma unroll
        for (int i = 0; i < (ATOT + NT - 1) / NT; i++) {
            int idx = tid + i * NT;
            if (idx < ATOT) {
                int row = idx / ACH, c4 = idx % ACH;
                cp16(&As[row * ASTR + c4 * 4], A + (size_t)(bm + row) * Kc + c4 * 4, (bm + row) < M);
            }
        }
#pragma unroll
        for (int i = 0; i < BTOT / NT; i++) {
            int idx = tid + i * NT;
            int row = idx / BCH, c4 = idx % BCH;
            cp16(&Bs[row * BSTR + c4 * 4], W + (size_t)row * Nc + bn + c4 * 4, true);
        }
        cp_commit();

        for (int t = 0; t < nkt; t++) {
            if (t + 1 < nkt) {
                int k0 = (t + 1) * BKT;
                int buf = (t + 1) & 1;
#pragma unroll
                for (int i = 0; i < (ATOT + NT - 1) / NT; i++) {
                    int idx = tid + i * NT;
                    if (idx < ATOT) {
                        int row = idx / ACH, c4 = idx % ACH;
                        cp16(&As[buf * ABUF + row * ASTR + c4 * 4],
                             A + (size_t)(bm + row) * Kc + k0 + c4 * 4, (bm + row) < M);
                    }
                }
#pragma unroll
                for (int i = 0; i < BTOT / NT; i++) {
                    int idx = tid + i * NT;
                    int row = idx / BCH, c4 = idx % BCH;
                    cp16(&Bs[buf * BBUF + row * BSTR + c4 * 4],
                         W + (size_t)(k0 + row) * Nc + bn + c4 * 4, true);
                }
            }
            cp_commit();
            cp_wait1();
            __syncthreads();
            const float* as = As + (t & 1) * ABUF;
            const float* bs = Bs + (t & 1) * BBUF;
#pragma unroll
            for (int ks = 0; ks < NKS; ks++) {
                int k0 = ks * 8;
                int rb = warp_m * 16;
                uint32_t af[4];
                af[0] = f2tf(as[(rb + g)     * ASTR + k0 + tg]);
                af[1] = f2tf(as[(rb + g + 8) * ASTR + k0 + tg]);
                af[2] = f2tf(as[(rb + g)     * ASTR + k0 + tg + 4]);
                af[3] = f2tf(as[(rb + g + 8) * ASTR + k0 + tg + 4]);
#pragma unroll
                for (int tn = 0; tn < TN; tn++) {
                    int cb = warp_n * (TILEN / 8) + tn * 8;
                    uint32_t bf0 = f2tf(bs[(k0 + tg)     * BSTR + cb + g]);
                    uint32_t bf1 = f2tf(bs[(k0 + tg + 4) * BSTR + cb + g]);
                    asm volatile(
                        "mma.sync.aligned.m16n8k8.row.col.f32.tf32.tf32.f32 "
                        "{%0,%1,%2,%3}, {%4,%5,%6,%7}, {%8,%9}, {%0,%1,%2,%3};\n"
                        : "+f"(acc[tn][0]), "+f"(acc[tn][1]),
                          "+f"(acc[tn][2]), "+f"(acc[tn][3])
                        : "r"(af[0]), "r"(af[1]), "r"(af[2]), "r"(af[3]),
                          "r"(bf0), "r"(bf1));
                }
            }
            __syncthreads();
        }
        cp_waitall();

        int r0 = bm + warp_m * 16 + g;
#pragma unroll
        for (int tn = 0; tn < TN; tn++) {
            int c0 = bn + warp_n * (TILEN / 8) + tn * 8 + tg * 2;
#pragma unroll
            for (int half = 0; half < 2; half++) {
                int rr = r0 + half * 8;
                if (rr >= M) continue;
                float v0 = acc[tn][half * 2 + 0];
                float v1 = acc[tn][half * 2 + 1];
                if (bias) { v0 += bias[c0]; v1 += bias[c0 + 1]; }
                if (act == 1) { v0 = gelu_exact(v0); v1 = gelu_exact(v1); }
                if (addsrc) {
                    v0 += addsrc[(size_t)rr * Nc + c0];
                    v1 += addsrc[(size_t)rr * Nc + c0 + 1];
                }
                C[(size_t)rr * Nc + c0]     = v0;
                C[(size_t)rr * Nc + c0 + 1] = v1;
            }
        }
    }
    __syncthreads();
}

__device__ __forceinline__ void dev_gemm(const float* A, const float* W,
                                         const float* bias, const float* addsrc,
                                         float* C, int M, int Nc, int Kc, int act,
                                         float* s_u) {
    if (Nc >= 2304)      dev_gemm_t<256, 32>(A, W, bias, addsrc, C, M, Nc, Kc, act, s_u);
    else if (Kc >= 3072) dev_gemm_t<64, 64> (A, W, bias, addsrc, C, M, Nc, Kc, act, s_u);
    else                 dev_gemm_t<64, 32> (A, W, bias, addsrc, C, M, Nc, Kc, act, s_u);
}

// ---------------- fused slot attention (R12: pipelined 3-group staging) ----------------
__device__ void dev_fused(const float* __restrict__ qmat, const float* __restrict__ fn,
                          float* __restrict__ pupd, float* __restrict__ pmass,
                          float* __restrict__ masks, int write_upd, float* s_u) {
    float* s_tile = s_u + SM_TILE;
    float* s_q    = s_u + SM_Q;
    float* s_at   = s_u + SM_AT;
    float* s_mass = s_u + SM_MASS;
    int tid = threadIdx.x, lane = tid & 31, warp = tid >> 5;
    const float4* qsv = (const float4*)s_q;

    for (int u = blockIdx.x; u < NUNITS; u += NB) {
        int b = u % BB, ch = u / BB;
        int n0 = ch * CH_TOK;
        int n1 = n0 + CH_TOK; if (n1 > NN) n1 = NN;

        __syncthreads();
        {
            const float4* qb4 = (const float4*)(qmat + (size_t)b * KK * DD);
            float4* qd = (float4*)s_q;
            for (int i = tid; i < KK * DD / 4; i += NT) qd[i] = qb4[i];
        }
        if (tid < KK) s_mass[tid] = 0.f;
        float acc[KK][2];
#pragma unroll
        for (int k = 0; k < KK; k++) { acc[k][0] = 0.f; acc[k][1] = 0.f; }

        int srow = tid >> 4;
        int scb  = tid & 15;

        for (int tbase = n0; tbase < n1; tbase += TILE_TOK) {
            {
                bool rowok = (tbase + srow) < n1;
                const float* src = fn + ((size_t)b * NN + tbase + srow) * DD;
                float* dst = s_tile + srow * DD;
#pragma unroll
                for (int gph = 0; gph < 3; gph++) {
#pragma unroll
                    for (int i = 0; i < 4; i++) {
                        int c4 = gph * 64 + scb + 16 * i;
                        cp16(dst + c4 * 4, src + c4 * 4, rowok);
                    }
                    cp_commit();
                }
            }

            float p[2][KK];
#pragma unroll
            for (int tk = 0; tk < 2; tk++)
#pragma unroll
                for (int s = 0; s < KK; s++) p[tk][s] = 0.f;
            const float4* r0 = (const float4*)(s_tile + (warp * 2) * DD);
            const float4* r1 = (const float4*)(s_tile + (warp * 2 + 1) * DD);
#pragma unroll
            for (int st = 0; st < 3; st++) {
                if (st == 0) cp_wait_n<2>();
                else if (st == 1) cp_wait_n<1>();
                else cp_wait_n<0>();
                __syncthreads();
#pragma unroll
                for (int it = st * 2; it < st * 2 + 2; it++) {
                    int d4 = it * 32 + lane;
                    float4 k0 = r0[d4];
                    float4 k1 = r1[d4];
#pragma unroll
                    for (int s = 0; s < KK; s++) {
                        float4 qv = qsv[s * (DD / 4) + d4];
                        p[0][s] = fmaf(k0.x, qv.x, p[0][s]);
                        p[0][s] = fmaf(k0.y, qv.y, p[0][s]);
                        p[0][s] = fmaf(k0.z, qv.z, p[0][s]);
                        p[0][s] = fmaf(k0.w, qv.w, p[0][s]);
                        p[1][s] = fmaf(k1.x, qv.x, p[1][s]);
                        p[1][s] = fmaf(k1.y, qv.y, p[1][s]);
                        p[1][s] = fmaf(k1.z, qv.z, p[1][s]);
                        p[1][s] = fmaf(k1.w, qv.w, p[1][s]);
                    }
                }
            }
#pragma unroll
            for (int tk = 0; tk < 2; tk++)
#pragma unroll
                for (int s = 0; s < KK; s++)
#pragma unroll
                    for (int off = 16; off; off >>= 1)
                        p[tk][s] += __shfl_xor_sync(0xffffffffu, p[tk][s], off);
#pragma unroll
            for (int tk = 0; tk < 2; tk++) {
                int ntok = tbase + warp * 2 + tk;
                bool valid = ntok < n1;
                float mx = -1e30f;
#pragma unroll
                for (int s = 0; s < KK; s++) { p[tk][s] *= SCALE_QK; mx = fmaxf(mx, p[tk][s]); }
                float tot = 0.f;
                float e[KK];
#pragma unroll
                for (int s = 0; s < KK; s++) { e[s] = expf(p[tk][s] - mx); tot += e[s]; }
                float invt = 1.0f / tot;
                float mine = (valid && lane < KK) ? e[lane] * invt : 0.f;
                if (lane < KK) {
                    s_at[(warp * 2 + tk) * KK + lane] = mine;
                    if (write_upd) {
                        if (valid) atomicAdd(&s_mass[lane], mine);
                    } else if (valid) {
                        masks[((size_t)b * NN + ntok) * KK + lane] = mine;
                    }
                }
            }
            __syncthreads();

            if (write_upd) {
                if (tid < 384) {
                    const float2* tp = (const float2*)s_tile;
#pragma unroll 2
                    for (int j = 0; j < TILE_TOK; j++) {
                        float2 f = tp[j * (DD / 2) + tid];
                        const float4* aj = (const float4*)(s_at + j * KK);
                        float4 a0 = aj[0], a1 = aj[1], a2 = aj[2];
                        acc[0][0]  = fmaf(a0.x, f.x, acc[0][0]);  acc[0][1]  = fmaf(a0.x, f.y, acc[0][1]);
                        acc[1][0]  = fmaf(a0.y, f.x, acc[1][0]);  acc[1][1]  = fmaf(a0.y, f.y, acc[1][1]);
                        acc[2][0]  = fmaf(a0.z, f.x, acc[2][0]);  acc[2][1]  = fmaf(a0.z, f.y, acc[2][1]);
                        acc[3][0]  = fmaf(a0.w, f.x, acc[3][0]);  acc[3][1]  = fmaf(a0.w, f.y, acc[3][1]);
                        acc[4][0]  = fmaf(a1.x, f.x, acc[4][0]);  acc[4][1]  = fmaf(a1.x, f.y, acc[4][1]);
                        acc[5][0]  = fmaf(a1.y, f.x, acc[5][0]);  acc[5][1]  = fmaf(a1.y, f.y, acc[5][1]);
                        acc[6][0]  = fmaf(a1.z, f.x, acc[6][0]);  acc[6][1]  = fmaf(a1.z, f.y, acc[6][1]);
                        acc[7][0]  = fmaf(a1.w, f.x, acc[7][0]);  acc[7][1]  = fmaf(a1.w, f.y, acc[7][1]);
                        acc[8][0]  = fmaf(a2.x, f.x, acc[8][0]);  acc[8][1]  = fmaf(a2.x, f.y, acc[8][1]);
                        acc[9][0]  = fmaf(a2.y, f.x, acc[9][0]);  acc[9][1]  = fmaf(a2.y, f.y, acc[9][1]);
                        acc[10][0] = fmaf(a2.z, f.x, acc[10][0]); acc[10][1] = fmaf(a2.z, f.y, acc[10][1]);
                        acc[11][0] = fmaf(a2.w, f.x, acc[11][0]); acc[11][1] = fmaf(a2.w, f.y, acc[11][1]);
                    }
                }
                __syncthreads();
            }
        }
        if (write_upd) {
            if (tid < 384) {
                float* pu = pupd + (size_t)u * KK * DD;
#pragma unroll
                for (int k = 0; k < KK; k++) {
                    pu[k * DD + 2 * tid]     = acc[k][0];
                    pu[k * DD + 2 * tid + 1] = acc[k][1];
                }
            }
            if (tid < KK) pmass[u * KK + tid] = s_mass[tid];
        }
        __syncthreads();
    }
    __syncthreads();
}

// ---------------- reduce partials ----------------
__device__ void dev_reduce(const float* __restrict__ pupd, const float* __restrict__ pmass,
                           float* __restrict__ ub) {
    int tid = threadIdx.x;
    for (int r = blockIdx.x; r < SROWS; r += NB) {
        int b = r / KK, k = r % KK;
        float m = 0.f;
#pragma unroll
        for (int ch = 0; ch < NCH; ch++) m += pmass[(ch * BB + b) * KK + k];
        float inv = 1.0f / fmaxf(m, 1e-8f);
        for (int d = tid; d < DD; d += NT) {
            float s = 0.f;
#pragma unroll
            for (int ch = 0; ch < NCH; ch++)
                s += pupd[(size_t)(ch * BB + b) * KK * DD + k * DD + d];
            ub[(size_t)r * DD + d] = s * inv;
        }
    }
}

// ---------------- tiny multi-head self-attention ----------------
__device__ void dev_blockattn(const float* __restrict__ qkv, float* __restrict__ obuf,
                              float* s_u) {
    float* qs = s_u;
    float* ks = s_u + 1152;
    float* vs = s_u + 2304;
    float* sc = s_u + 3456;
    float* at = s_u + 3600;
    int tid = threadIdx.x;
    for (int u = blockIdx.x; u < BB * HH; u += NB) {
        int b = u >> 3, h = u & 7;
        __syncthreads();
        for (int idx = tid; idx < KK * HD; idx += NT) {
            int r = idx / HD, c = idx % HD;
            size_t base = ((size_t)(b * KK + r)) * (3 * DD) + h * HD + c;
            qs[r * HD + c] = qkv[base];
            ks[r * HD + c] = qkv[base + DD];
            vs[r * HD + c] = qkv[base + 2 * DD];
        }
        __syncthreads();
        if (tid < 144) {
            int i = tid / KK, j = tid % KK;
            float s = 0.f;
#pragma unroll
            for (int d = 0; d < HD; d++) s = fmaf(qs[i * HD + d], ks[j * HD + d], s);
            sc[i * KK + j] = s * SCALE_HD;
        }
        __syncthreads();
        if (tid < 144) {
            int i = tid / KK, j = tid % KK;
            float mx = -1e30f;
#pragma unroll
            for (int jj = 0; jj < KK; jj++) mx = fmaxf(mx, sc[i * KK + jj]);
            float tot = 0.f;
#pragma unroll
            for (int jj = 0; jj < KK; jj++) tot += expf(sc[i * KK + jj] - mx);
            at[i * KK + j] = expf(sc[i * KK + j] - mx) / tot;
        }
        __syncthreads();
        for (int idx = tid; idx < KK * HD; idx += NT) {
            int r = idx / HD, d = idx % HD;
            float s = 0.f;
#pragma unroll
            for (int jj = 0; jj < KK; jj++) s = fmaf(at[r * KK + jj], vs[jj * HD + d], s);
            obuf[((size_t)(b * KK + r)) * DD + h * HD + d] = s;
        }
        __syncthreads();
    }
    __syncthreads();
}

// ---------------- transpose 768x768 ----------------
__device__ void dev_transpose(const float* __restrict__ in, float* __restrict__ out,
                              float* s_u) {
    float* tile = s_u;
    int tx = threadIdx.x & 31, ty = threadIdx.x >> 5;
    for (int tix = blockIdx.x; tix < 24 * 24; tix += NB) {
        int bx = (tix % 24) * 32, by = (tix / 24) * 32;
        __syncthreads();
#pragma unroll
        for (int dy = 0; dy < 32; dy += 16)
            tile[(ty + dy) * 33 + tx] = in[(size_t)(by + ty + dy) * DD + bx + tx];
        __syncthreads();
#pragma unroll
        for (int dy = 0; dy < 32; dy += 16)
            out[(size_t)(bx + ty + dy) * DD + by + tx] = tile[tx * 33 + ty + dy];
    }
    __syncthreads();
}

__device__ void dev_copy(float* __restrict__ dst, const float* __restrict__ src, int n4) {
    for (int i = blockIdx.x * NT + threadIdx.x; i < n4; i += NB * NT)
        ((float4*)dst)[i] = ((const float4*)src)[i];
}

// ---------------- the megakernel ----------------
__global__ __launch_bounds__(NT, 1)
void mega_kernel(const float* features, const float* slots_init,
                 const float* nf_g, const float* nf_b,
                 const float* ns_g, const float* ns_b,
                 const float* Wq, const float* Wk, const float* Wv,
                 const float* mg, const float* mb,
                 const float* mW1, const float* mb1,
                 const float* mW2, const float* mb2,
                 const float* b_ln1g, const float* b_ln1b,
                 const float* b_Wqkv, const float* b_bqkv,
                 const float* b_Wo, const float* b_bo,
                 const float* b_ln2g, const float* b_ln2b,
                 const float* b_W1, const float* b_b1,
                 const float* b_W2, const float* b_b2,
                 float* out) {
    extern __shared__ __align__(16) float s_u[];

    dev_transpose(Wk, g_wkt, s_u);
    dev_ln(features, nullptr, nf_g, nf_b, g_fn, BNROWS);
    dev_copy(g_slots, slots_init, SROWS * DD / 4);
    gridbar();
    dev_gemm(Wq, g_wkt, nullptr, nullptr, g_wqk, DD, DD, DD, 0, s_u);
    gridbar();

    for (int t = 0; t < TT; t++) {
        const float* ln1g = b_ln1g + (size_t)t * DD;
        const float* ln1b = b_ln1b + (size_t)t * DD;
        const float* Wqkv = b_Wqkv + (size_t)t * DD * 3 * DD;
        const float* bqkv = b_bqkv + (size_t)t * 3 * DD;
        const float* Wo   = b_Wo   + (size_t)t * DD * DD;
        const float* bo   = b_bo   + (size_t)t * DD;
        const float* ln2g = b_ln2g + (size_t)t * DD;
        const float* ln2b = b_ln2b + (size_t)t * DD;
        const float* W1   = b_W1   + (size_t)t * DD * 4 * DD;
        const float* b1   = b_b1   + (size_t)t * 4 * DD;
        const float* W2   = b_W2   + (size_t)t * 4 * DD * DD;
        const float* b2   = b_b2   + (size_t)t * DD;

        dev_ln(g_slots, nullptr, ns_g, ns_b, g_sn, SROWS);
        gridbar();
        dev_gemm(g_sn, g_wqk, nullptr, nullptr, g_q, SROWS, DD, DD, 0, s_u);
        dev_ln(g_sn, nullptr, ln1g, ln1b, g_h1, SROWS);
        gridbar();
        dev_fused(g_q, g_fn, g_pupd, g_pmass, nullptr, 1, s_u);
        dev_gemm(g_h1, Wqkv, bqkv, nullptr, g_qkvb, SROWS, 3 * DD, DD, 0, s_u);
        gridbar();
        dev_reduce(g_pupd, g_pmass, g_ub);
        dev_blockattn(g_qkvb, g_ob, s_u);
        gridbar();
        dev_gemm(g_ub, Wv, nullptr, nullptr, g_upd, SROWS, DD, DD, 0, s_u);
        dev_gemm(g_ob, Wo, bo, g_sn, g_x1, SROWS, DD, DD, 0, s_u);
        gridbar();
        dev_ln(g_x1, nullptr, ln2g, ln2b, g_h2, SROWS);
        gridbar();
        dev_gemm(g_h2, W1, b1, nullptr, g_g1, SROWS, 4 * DD, DD, 1, s_u);
        gridbar();
        dev_gemm(g_g1, W2, b2, g_x1, g_x2, SROWS, DD, 4 * DD, 0, s_u);
        gridbar();
        dev_ln(g_upd, g_x2, mg, mb, g_h3, SROWS);
        gridbar();
        dev_gemm(g_h3, mW1, mb1, nullptr, g_g2, SROWS, 4 * DD, DD, 1, s_u);
        gridbar();
        dev_gemm(g_g2, mW2, mb2, g_slots, g_slots, SROWS, DD, 4 * DD, 0, s_u);
        gridbar();
    }

    dev_ln(g_slots, nullptr, ns_g, ns_b, g_sn, SROWS);
    gridbar();
    dev_gemm(g_sn, g_wqk, nullptr, nullptr, g_q, SROWS, DD, DD, 0, s_u);
    dev_copy(out, g_slots, SROWS * DD / 4);
    gridbar();
    dev_fused(g_q, g_fn, nullptr, nullptr, out + (size_t)SROWS * DD, 0, s_u);
}

// ---------------- host ----------------
extern "C" void kernel_launch(void* const* d_in, const int* in_sizes, int n_in,
                              void* d_out, int out_size) {
    const float* features  = (const float*)d_in[0];
    const float* slots_init= (const float*)d_in[1];
    const float* nf_g = (const float*)d_in[2];
    const float* nf_b = (const float*)d_in[3];
    const float* ns_g = (const float*)d_in[4];
    const float* ns_b = (const float*)d_in[5];
    const float* Wq   = (const float*)d_in[6];
    const float* Wk   = (const float*)d_in[7];
    const float* Wv   = (const float*)d_in[8];
    const float* mg   = (const float*)d_in[9];
    const float* mb   = (const float*)d_in[10];
    const float* mW1  = (const float*)d_in[11];
    const float* mb1  = (const float*)d_in[12];
    const float* mW2  = (const float*)d_in[13];
    const float* mb2  = (const float*)d_in[14];
    const float* b_ln1g = (const float*)d_in[15];
    const float* b_ln1b = (const float*)d_in[16];
    const float* b_Wqkv = (const float*)d_in[17];
    const float* b_bqkv = (const float*)d_in[18];
    const float* b_Wo   = (const float*)d_in[19];
    const float* b_bo   = (const float*)d_in[20];
    const float* b_ln2g = (const float*)d_in[21];
    const float* b_ln2b = (const float*)d_in[22];
    const float* b_W1   = (const float*)d_in[23];
    const float* b_b1   = (const float*)d_in[24];
    const float* b_W2   = (const float*)d_in[25];
    const float* b_b2   = (const float*)d_in[26];

    static int configured = 0;
    if (!configured) {
        cudaFuncSetAttribute(mega_kernel, cudaFuncAttributeMaxDynamicSharedMemorySize,
                             SMEM_BYTES);
        configured = 1;
    }

    mega_kernel<<<NB, NT, SMEM_BYTES>>>(features, slots_init, nf_g, nf_b, ns_g, ns_b,
                                        Wq, Wk, Wv, mg, mb, mW1, mb1, mW2, mb2,
                                        b_ln1g, b_ln1b, b_Wqkv, b_bqkv, b_Wo, b_bo,
                                        b_ln2g, b_ln2b, b_W1, b_b1, b_W2, b_b2,
                                        (float*)d_out);
}

// round 16
// speedup vs baseline: 1.1338x; 1.0011x over previous
#include <cuda_runtime.h>
#include <math.h>
#include <stdint.h>

// ---------------- problem constants ----------------
#define BB 32
#define NN 1369
#define DD 768
#define KK 12
#define TT 3
#define HH 8
#define HD 96
#define BNROWS (BB * NN)          // 43808
#define SROWS  (BB * KK)          // 384
#define NB 148                    // persistent grid = #SMs
#define NT 512
#define NWARP 16
#define NCH 9
#define CH_TOK 153
#define NUNITS (BB * NCH)         // 288
#define TILE_TOK 32
#define TSTR 776                  // tile row stride (776 % 32 = 8 -> conflict-free B frags)
#define ATSTR 33                  // s_at row stride
#define SCALE_QK 0.03608439182435161f
#define SCALE_HD 0.10206207261596575f

// dynamic smem layout (floats)
#define SM_TILE 0                  // 32*776 = 24832
#define SM_Q    24832              // 12*768 = 9216
#define SM_AT   34048              // 16*33 = 528 (slots x tokens, transposed)
#define SM_MASS 34576              // 16
#define SM_TOTALF 34592
#define SMEM_BYTES (SM_TOTALF * 4) // 138368 B

// ---------------- scratch (device globals) ----------------
__device__ float g_wkt [DD * DD];
__device__ float g_wqk [DD * DD];
__device__ float g_fn  [(size_t)BNROWS * DD];
__device__ float g_sn  [SROWS * DD];
__device__ float g_q   [SROWS * DD];
__device__ float g_pupd[(size_t)NUNITS * KK * DD];
__device__ float g_pmass[NUNITS * KK];
__device__ float g_ub  [SROWS * DD];
__device__ float g_upd [SROWS * DD];
__device__ float g_h1  [SROWS * DD];
__device__ float g_qkvb[SROWS * 3 * DD];
__device__ float g_ob  [SROWS * DD];
__device__ float g_x1  [SROWS * DD];
__device__ float g_h2  [SROWS * DD];
__device__ float g_g1  [SROWS * 4 * DD];
__device__ float g_x2  [SROWS * DD];
__device__ float g_h3  [SROWS * DD];
__device__ float g_g2  [SROWS * 4 * DD];
__device__ float g_slots[SROWS * DD];

__device__ int g_bar_count = 0;
__device__ int g_bar_gen   = 0;

// ---------------- helpers ----------------
__device__ __forceinline__ float gelu_exact(float x) {
    return 0.5f * x * (1.0f + erff(x * 0.70710678118654752f));
}
__device__ __forceinline__ uint32_t f2tf(float x) {
    uint32_t y;
    asm("cvt.rna.tf32.f32 %0, %1;" : "=r"(y) : "f"(x));
    return y;
}
__device__ __forceinline__ void cp16(void* smem_dst, const void* gmem_src, bool pred) {
    uint32_t s = (uint32_t)__cvta_generic_to_shared(smem_dst);
    int sz = pred ? 16 : 0;
    asm volatile("cp.async.ca.shared.global [%0], [%1], 16, %2;\n"
                 :: "r"(s), "l"(gmem_src), "r"(sz));
}
__device__ __forceinline__ void cp_commit() { asm volatile("cp.async.commit_group;\n"); }
template<int N>
__device__ __forceinline__ void cp_wait_n() { asm volatile("cp.async.wait_group %0;\n" :: "n"(N) : "memory"); }
__device__ __forceinline__ void cp_wait1()  { asm volatile("cp.async.wait_group 1;\n"); }
__device__ __forceinline__ void cp_waitall(){ asm volatile("cp.async.wait_all;\n" ::: "memory"); }

// ---------------- software grid barrier (volatile-load spin) ----------------
__device__ __forceinline__ void gridbar() {
    __syncthreads();
    if (threadIdx.x == 0) {
        __threadfence();
        int gen = *(volatile int*)&g_bar_gen;
        if (atomicAdd(&g_bar_count, 1) == NB - 1) {
            g_bar_count = 0;
            __threadfence();
            atomicAdd(&g_bar_gen, 1);
        } else {
            while (*(volatile int*)&g_bar_gen == gen) { __nanosleep(64); }
        }
        __threadfence();
    }
    __syncthreads();
}

// ---------------- LayerNorm: warp per row, rows spread across blocks first ----------------
__device__ void dev_ln(const float* __restrict__ x, const float* __restrict__ x2,
                       const float* __restrict__ gam, const float* __restrict__ bet,
                       float* __restrict__ out, int rows) {
    int warp = threadIdx.x >> 5, lane = threadIdx.x & 31;
    for (int r = blockIdx.x + NB * warp; r < rows; r += NB * NWARP) {
        const float4* xr = (const float4*)(x + (size_t)r * DD);
        const float4* x2r = x2 ? (const float4*)(x2 + (size_t)r * DD) : nullptr;
        float4 v[6];
        float s = 0.f;
#pragma unroll
        for (int i = 0; i < 6; i++) {
            int d4 = lane + i * 32;
            float4 t = xr[d4];
            if (x2r) { float4 u = x2r[d4]; t.x += u.x; t.y += u.y; t.z += u.z; t.w += u.w; }
            v[i] = t;
            s += t.x + t.y + t.z + t.w;
        }
#pragma unroll
        for (int off = 16; off; off >>= 1) s += __shfl_xor_sync(0xffffffffu, s, off);
        float mean = s * (1.0f / DD);
        float s2 = 0.f;
#pragma unroll
        for (int i = 0; i < 6; i++) {
            float dx = v[i].x - mean, dy = v[i].y - mean, dz = v[i].z - mean, dw = v[i].w - mean;
            s2 += dx * dx + dy * dy + dz * dz + dw * dw;
        }
#pragma unroll
        for (int off = 16; off; off >>= 1) s2 += __shfl_xor_sync(0xffffffffu, s2, off);
        float inv = rsqrtf(s2 * (1.0f / DD) + 1e-5f);
        float4* o4 = (float4*)(out + (size_t)r * DD);
#pragma unroll
        for (int i = 0; i < 6; i++) {
            int d4 = lane + i * 32;
            float4 gv = ((const float4*)gam)[d4];
            float4 bv = ((const float4*)bet)[d4];
            float4 t;
            t.x = (v[i].x - mean) * inv * gv.x + bv.x;
            t.y = (v[i].y - mean) * inv * gv.y + bv.y;
            t.z = (v[i].z - mean) * inv * gv.z + bv.z;
            t.w = (v[i].w - mean) * inv * gv.w + bv.w;
            o4[d4] = t;
        }
    }
}

// ---------------- TF32 GEMM: 32xTILEN tiles, 16 warps, BK templated ----------------
template<int TILEN, int BKT>
__device__ void dev_gemm_t(const float* __restrict__ A, const float* __restrict__ W,
                           const float* __restrict__ bias, const float* __restrict__ addsrc,
                           float* __restrict__ C, int M, int Nc, int Kc, int act,
                           float* s_u) {
    constexpr int ASTR = BKT + 4;
    constexpr int ABUF = 32 * ASTR;
    constexpr int ACH  = BKT / 4;
    constexpr int ATOT = 32 * ACH;
    constexpr int BSTR = TILEN + 8;
    constexpr int BBUF = BKT * BSTR;
    constexpr int BCH  = TILEN / 4;
    constexpr int BTOT = BKT * BCH;
    constexpr int TN   = TILEN / 64;
    constexpr int NKS  = BKT / 8;
    float* As = s_u;
    float* Bs = s_u + 2 * ABUF;
    int tid = threadIdx.x, lane = tid & 31, warp = tid >> 5;
    int warp_m = warp >> 3, warp_n = warp & 7;
    int g = lane >> 2, tg = lane & 3;
    int ntn = Nc / TILEN, ntm = (M + 31) >> 5;
    int nkt = Kc / BKT;

    for (int tix = blockIdx.x; tix < ntm * ntn; tix += NB) {
        int bm = (tix / ntn) << 5, bn = (tix % ntn) * TILEN;
        float acc[TN][4];
#pragma unroll
        for (int i = 0; i < TN; i++)
#pragma unroll
            for (int j = 0; j < 4; j++) acc[i][j] = 0.f;

        __syncthreads();
#pragma unroll
        for (int i = 0; i < (ATOT + NT - 1) / NT; i++) {
            int idx = tid + i * NT;
            if (idx < ATOT) {
                int row = idx / ACH, c4 = idx % ACH;
                cp16(&As[row * ASTR + c4 * 4], A + (size_t)(bm + row) * Kc + c4 * 4, (bm + row) < M);
            }
        }
#pragma unroll
        for (int i = 0; i < BTOT / NT; i++) {
            int idx = tid + i * NT;
            int row = idx / BCH, c4 = idx % BCH;
            cp16(&Bs[row * BSTR + c4 * 4], W + (size_t)row * Nc + bn + c4 * 4, true);
        }
        cp_commit();

        for (int t = 0; t < nkt; t++) {
            if (t + 1 < nkt) {
                int k0 = (t + 1) * BKT;
                int buf = (t + 1) & 1;
#pragma unroll
                for (int i = 0; i < (ATOT + NT - 1) / NT; i++) {
                    int idx = tid + i * NT;
                    if (idx < ATOT) {
                        int row = idx / ACH, c4 = idx % ACH;
                        cp16(&As[buf * ABUF + row * ASTR + c4 * 4],
                             A + (size_t)(bm + row) * Kc + k0 + c4 * 4, (bm + row) < M);
                    }
                }
#pragma unroll
                for (int i = 0; i < BTOT / NT; i++) {
                    int idx = tid + i * NT;
                    int row = idx / BCH, c4 = idx % BCH;
                    cp16(&Bs[buf * BBUF + row * BSTR + c4 * 4],
                         W + (size_t)(k0 + row) * Nc + bn + c4 * 4, true);
                }
            }
            cp_commit();
            cp_wait1();
            __syncthreads();
            const float* as = As + (t & 1) * ABUF;
            const float* bs = Bs + (t & 1) * BBUF;
#pragma unroll
            for (int ks = 0; ks < NKS; ks++) {
                int k0 = ks * 8;
                int rb = warp_m * 16;
                uint32_t af[4];
                af[0] = f2tf(as[(rb + g)     * ASTR + k0 + tg]);
                af[1] = f2tf(as[(rb + g + 8) * ASTR + k0 + tg]);
                af[2] = f2tf(as[(rb + g)     * ASTR + k0 + tg + 4]);
                af[3] = f2tf(as[(rb + g + 8) * ASTR + k0 + tg + 4]);
#pragma unroll
                for (int tn = 0; tn < TN; tn++) {
                    int cb = warp_n * (TILEN / 8) + tn * 8;
                    uint32_t bf0 = f2tf(bs[(k0 + tg)     * BSTR + cb + g]);
                    uint32_t bf1 = f2tf(bs[(k0 + tg + 4) * BSTR + cb + g]);
                    asm volatile(
                        "mma.sync.aligned.m16n8k8.row.col.f32.tf32.tf32.f32 "
                        "{%0,%1,%2,%3}, {%4,%5,%6,%7}, {%8,%9}, {%0,%1,%2,%3};\n"
                        : "+f"(acc[tn][0]), "+f"(acc[tn][1]),
                          "+f"(acc[tn][2]), "+f"(acc[tn][3])
                        : "r"(af[0]), "r"(af[1]), "r"(af[2]), "r"(af[3]),
                          "r"(bf0), "r"(bf1));
                }
            }
            __syncthreads();
        }
        cp_waitall();

        int r0 = bm + warp_m * 16 + g;
#pragma unroll
        for (int tn = 0; tn < TN; tn++) {
            int c0 = bn + warp_n * (TILEN / 8) + tn * 8 + tg * 2;
#pragma unroll
            for (int half = 0; half < 2; half++) {
                int rr = r0 + half * 8;
                if (rr >= M) continue;
                float v0 = acc[tn][half * 2 + 0];
                float v1 = acc[tn][half * 2 + 1];
                if (bias) { v0 += bias[c0]; v1 += bias[c0 + 1]; }
                if (act == 1) { v0 = gelu_exact(v0); v1 = gelu_exact(v1); }
                if (addsrc) {
                    v0 += addsrc[(size_t)rr * Nc + c0];
                    v1 += addsrc[(size_t)rr * Nc + c0 + 1];
                }
                C[(size_t)rr * Nc + c0]     = v0;
                C[(size_t)rr * Nc + c0 + 1] = v1;
            }
        }
    }
    __syncthreads();
}

__device__ __forceinline__ void dev_gemm(const float* A, const float* W,
                                         const float* bias, const float* addsrc,
                                         float* C, int M, int Nc, int Kc, int act,
                                         float* s_u) {
    if (Nc >= 2304)      dev_gemm_t<256, 32>(A, W, bias, addsrc, C, M, Nc, Kc, act, s_u);
    else if (Kc >= 3072) dev_gemm_t<64, 64> (A, W, bias, addsrc, C, M, Nc, Kc, act, s_u);
    else                 dev_gemm_t<64, 32> (A, W, bias, addsrc, C, M, Nc, Kc, act, s_u);
}

// ---------------- fused slot attention (MMA accumulation) ----------------
__device__ void dev_fused(const float* __restrict__ qmat, const float* __restrict__ fn,
                          float* __restrict__ pupd, float* __restrict__ pmass,
                          float* __restrict__ masks, int write_upd, float* s_u) {
    float* s_tile = s_u + SM_TILE;
    float* s_q    = s_u + SM_Q;
    float* s_at   = s_u + SM_AT;     // [16][ATSTR] slots x tokens
    float* s_mass = s_u + SM_MASS;
    int tid = threadIdx.x, lane = tid & 31, warp = tid >> 5;
    int g = lane >> 2, tg = lane & 3;
    const float4* qsv = (const float4*)s_q;

    for (int u = blockIdx.x; u < NUNITS; u += NB) {
        int b = u % BB, ch = u / BB;
        int n0 = ch * CH_TOK;
        int n1 = n0 + CH_TOK; if (n1 > NN) n1 = NN;

        __syncthreads();
        {
            const float4* qb4 = (const float4*)(qmat + (size_t)b * KK * DD);
            float4* qd = (float4*)s_q;
            for (int i = tid; i < KK * DD / 4; i += NT) qd[i] = qb4[i];
        }
        if (tid < KK) s_mass[tid] = 0.f;
        // zero pad rows 12..15 of s_at (contiguous [12*ATSTR, 16*ATSTR))
        if (tid < 4 * ATSTR) s_at[12 * ATSTR + tid] = 0.f;
        float macc[6][4];
#pragma unroll
        for (int i = 0; i < 6; i++)
#pragma unroll
            for (int j = 0; j < 4; j++) macc[i][j] = 0.f;

        int srow = tid >> 4;
        int scb  = tid & 15;

        for (int tbase = n0; tbase < n1; tbase += TILE_TOK) {
            {
                bool rowok = (tbase + srow) < n1;
                const float* src = fn + ((size_t)b * NN + tbase + srow) * DD;
                float* dst = s_tile + srow * TSTR;
#pragma unroll
                for (int gph = 0; gph < 3; gph++) {
#pragma unroll
                    for (int i = 0; i < 4; i++) {
                        int c4 = gph * 64 + scb + 16 * i;
                        cp16(dst + c4 * 4, src + c4 * 4, rowok);
                    }
                    cp_commit();
                }
            }

            float p[2][KK];
#pragma unroll
            for (int tk = 0; tk < 2; tk++)
#pragma unroll
                for (int s = 0; s < KK; s++) p[tk][s] = 0.f;
            const float4* r0 = (const float4*)(s_tile + (warp * 2) * TSTR);
            const float4* r1 = (const float4*)(s_tile + (warp * 2 + 1) * TSTR);
#pragma unroll
            for (int st = 0; st < 3; st++) {
                if (st == 0) cp_wait_n<2>();
                else if (st == 1) cp_wait_n<1>();
                else cp_wait_n<0>();
                __syncthreads();
#pragma unroll
                for (int it = st * 2; it < st * 2 + 2; it++) {
                    int d4 = it * 32 + lane;
                    float4 k0 = r0[d4];
                    float4 k1 = r1[d4];
#pragma unroll
                    for (int s = 0; s < KK; s++) {
                        float4 qv = qsv[s * (DD / 4) + d4];
                        p[0][s] = fmaf(k0.x, qv.x, p[0][s]);
                        p[0][s] = fmaf(k0.y, qv.y, p[0][s]);
                        p[0][s] = fmaf(k0.z, qv.z, p[0][s]);
                        p[0][s] = fmaf(k0.w, qv.w, p[0][s]);
                        p[1][s] = fmaf(k1.x, qv.x, p[1][s]);
                        p[1][s] = fmaf(k1.y, qv.y, p[1][s]);
                        p[1][s] = fmaf(k1.z, qv.z, p[1][s]);
                        p[1][s] = fmaf(k1.w, qv.w, p[1][s]);
                    }
                }
            }
#pragma unroll
            for (int tk = 0; tk < 2; tk++)
#pragma unroll
                for (int s = 0; s < KK; s++)
#pragma unroll
                    for (int off = 16; off; off >>= 1)
                        p[tk][s] += __shfl_xor_sync(0xffffffffu, p[tk][s], off);
#pragma unroll
            for (int tk = 0; tk < 2; tk++) {
                int ntok = tbase + warp * 2 + tk;
                bool valid = ntok < n1;
                float mx = -1e30f;
#pragma unroll
                for (int s = 0; s < KK; s++) { p[tk][s] *= SCALE_QK; mx = fmaxf(mx, p[tk][s]); }
                float tot = 0.f;
                float e[KK];
#pragma unroll
                for (int s = 0; s < KK; s++) { e[s] = expf(p[tk][s] - mx); tot += e[s]; }
                float invt = 1.0f / tot;
                float mine = (valid && lane < KK) ? e[lane] * invt : 0.f;
                if (lane < KK) {
                    s_at[lane * ATSTR + (warp * 2 + tk)] = mine;   // transposed
                    if (write_upd) {
                        if (valid) atomicAdd(&s_mass[lane], mine);
                    } else if (valid) {
                        masks[((size_t)b * NN + ntok) * KK + lane] = mine;
                    }
                }
            }
            __syncthreads();

            // ---- accumulation via tensor cores: pupd += s_at[16,32] @ tile[32,768] ----
            if (write_upd) {
#pragma unroll
                for (int ks = 0; ks < 4; ks++) {
                    int k0 = ks * 8;
                    uint32_t af[4];
                    af[0] = f2tf(s_at[(g)     * ATSTR + k0 + tg]);
                    af[1] = f2tf(s_at[(g + 8) * ATSTR + k0 + tg]);
                    af[2] = f2tf(s_at[(g)     * ATSTR + k0 + tg + 4]);
                    af[3] = f2tf(s_at[(g + 8) * ATSTR + k0 + tg + 4]);
#pragma unroll
                    for (int nf = 0; nf < 6; nf++) {
                        int nb = warp * 48 + nf * 8;
                        uint32_t bf0 = f2tf(s_tile[(k0 + tg)     * TSTR + nb + g]);
                        uint32_t bf1 = f2tf(s_tile[(k0 + tg + 4) * TSTR + nb + g]);
                        asm volatile(
                            "mma.sync.aligned.m16n8k8.row.col.f32.tf32.tf32.f32 "
                            "{%0,%1,%2,%3}, {%4,%5,%6,%7}, {%8,%9}, {%0,%1,%2,%3};\n"
                            : "+f"(macc[nf][0]), "+f"(macc[nf][1]),
                              "+f"(macc[nf][2]), "+f"(macc[nf][3])
                            : "r"(af[0]), "r"(af[1]), "r"(af[2]), "r"(af[3]),
                              "r"(bf0), "r"(bf1));
                    }
                }
            }
            __syncthreads();
        }
        if (write_upd) {
            float* pu = pupd + (size_t)u * KK * DD;
#pragma unroll
            for (int nf = 0; nf < 6; nf++) {
                int c0 = warp * 48 + nf * 8 + tg * 2;
                // row g (slots 0..7 always valid)
                pu[(size_t)g * DD + c0]     = macc[nf][0];
                pu[(size_t)g * DD + c0 + 1] = macc[nf][1];
                if (g + 8 < KK) {
                    pu[(size_t)(g + 8) * DD + c0]     = macc[nf][2];
                    pu[(size_t)(g + 8) * DD + c0 + 1] = macc[nf][3];
                }
            }
            if (tid < KK) pmass[u * KK + tid] = s_mass[tid];
        }
        __syncthreads();
    }
    __syncthreads();
}

// ---------------- reduce partials ----------------
__device__ void dev_reduce(const float* __restrict__ pupd, const float* __restrict__ pmass,
                           float* __restrict__ ub) {
    int tid = threadIdx.x;
    for (int r = blockIdx.x; r < SROWS; r += NB) {
        int b = r / KK, k = r % KK;
        float m = 0.f;
#pragma unroll
        for (int ch = 0; ch < NCH; ch++) m += pmass[(ch * BB + b) * KK + k];
        float inv = 1.0f / fmaxf(m, 1e-8f);
        for (int d = tid; d < DD; d += NT) {
            float s = 0.f;
#pragma unroll
            for (int ch = 0; ch < NCH; ch++)
                s += pupd[(size_t)(ch * BB + b) * KK * DD + k * DD + d];
            ub[(size_t)r * DD + d] = s * inv;
        }
    }
}

// ---------------- tiny multi-head self-attention ----------------
__device__ void dev_blockattn(const float* __restrict__ qkv, float* __restrict__ obuf,
                              float* s_u) {
    float* qs = s_u;
    float* ks = s_u + 1152;
    float* vs = s_u + 2304;
    float* sc = s_u + 3456;
    float* at = s_u + 3600;
    int tid = threadIdx.x;
    for (int u = blockIdx.x; u < BB * HH; u += NB) {
        int b = u >> 3, h = u & 7;
        __syncthreads();
        for (int idx = tid; idx < KK * HD; idx += NT) {
            int r = idx / HD, c = idx % HD;
            size_t base = ((size_t)(b * KK + r)) * (3 * DD) + h * HD + c;
            qs[r * HD + c] = qkv[base];
            ks[r * HD + c] = qkv[base + DD];
            vs[r * HD + c] = qkv[base + 2 * DD];
        }
        __syncthreads();
        if (tid < 144) {
            int i = tid / KK, j = tid % KK;
            float s = 0.f;
#pragma unroll
            for (int d = 0; d < HD; d++) s = fmaf(qs[i * HD + d], ks[j * HD + d], s);
            sc[i * KK + j] = s * SCALE_HD;
        }
        __syncthreads();
        if (tid < 144) {
            int i = tid / KK, j = tid % KK;
            float mx = -1e30f;
#pragma unroll
            for (int jj = 0; jj < KK; jj++) mx = fmaxf(mx, sc[i * KK + jj]);
            float tot = 0.f;
#pragma unroll
            for (int jj = 0; jj < KK; jj++) tot += expf(sc[i * KK + jj] - mx);
            at[i * KK + j] = expf(sc[i * KK + j] - mx) / tot;
        }
        __syncthreads();
        for (int idx = tid; idx < KK * HD; idx += NT) {
            int r = idx / HD, d = idx % HD;
            float s = 0.f;
#pragma unroll
            for (int jj = 0; jj < KK; jj++) s = fmaf(at[r * KK + jj], vs[jj * HD + d], s);
            obuf[((size_t)(b * KK + r)) * DD + h * HD + d] = s;
        }
        __syncthreads();
    }
    __syncthreads();
}

// ---------------- transpose 768x768 ----------------
__device__ void dev_transpose(const float* __restrict__ in, float* __restrict__ out,
                              float* s_u) {
    float* tile = s_u;
    int tx = threadIdx.x & 31, ty = threadIdx.x >> 5;
    for (int tix = blockIdx.x; tix < 24 * 24; tix += NB) {
        int bx = (tix % 24) * 32, by = (tix / 24) * 32;
        __syncthreads();
#pragma unroll
        for (int dy = 0; dy < 32; dy += 16)
            tile[(ty + dy) * 33 + tx] = in[(size_t)(by + ty + dy) * DD + bx + tx];
        __syncthreads();
#pragma unroll
        for (int dy = 0; dy < 32; dy += 16)
            out[(size_t)(bx + ty + dy) * DD + by + tx] = tile[tx * 33 + ty + dy];
    }
    __syncthreads();
}

__device__ void dev_copy(float* __restrict__ dst, const float* __restrict__ src, int n4) {
    for (int i = blockIdx.x * NT + threadIdx.x; i < n4; i += NB * NT)
        ((float4*)dst)[i] = ((const float4*)src)[i];
}

// ---------------- the megakernel ----------------
__global__ __launch_bounds__(NT, 1)
void mega_kernel(const float* features, const float* slots_init,
                 const float* nf_g, const float* nf_b,
                 const float* ns_g, const float* ns_b,
                 const float* Wq, const float* Wk, const float* Wv,
                 const float* mg, const float* mb,
                 const float* mW1, const float* mb1,
                 const float* mW2, const float* mb2,
                 const float* b_ln1g, const float* b_ln1b,
                 const float* b_Wqkv, const float* b_bqkv,
                 const float* b_Wo, const float* b_bo,
                 const float* b_ln2g, const float* b_ln2b,
                 const float* b_W1, const float* b_b1,
                 const float* b_W2, const float* b_b2,
                 float* out) {
    extern __shared__ __align__(16) float s_u[];

    dev_transpose(Wk, g_wkt, s_u);
    dev_ln(features, nullptr, nf_g, nf_b, g_fn, BNROWS);
    dev_copy(g_slots, slots_init, SROWS * DD / 4);
    gridbar();
    dev_gemm(Wq, g_wkt, nullptr, nullptr, g_wqk, DD, DD, DD, 0, s_u);
    gridbar();

    for (int t = 0; t < TT; t++) {
        const float* ln1g = b_ln1g + (size_t)t * DD;
        const float* ln1b = b_ln1b + (size_t)t * DD;
        const float* Wqkv = b_Wqkv + (size_t)t * DD * 3 * DD;
        const float* bqkv = b_bqkv + (size_t)t * 3 * DD;
        const float* Wo   = b_Wo   + (size_t)t * DD * DD;
        const float* bo   = b_bo   + (size_t)t * DD;
        const float* ln2g = b_ln2g + (size_t)t * DD;
        const float* ln2b = b_ln2b + (size_t)t * DD;
        const float* W1   = b_W1   + (size_t)t * DD * 4 * DD;
        const float* b1   = b_b1   + (size_t)t * 4 * DD;
        const float* W2   = b_W2   + (size_t)t * 4 * DD * DD;
        const float* b2   = b_b2   + (size_t)t * DD;

        dev_ln(g_slots, nullptr, ns_g, ns_b, g_sn, SROWS);
        gridbar();
        dev_gemm(g_sn, g_wqk, nullptr, nullptr, g_q, SROWS, DD, DD, 0, s_u);
        dev_ln(g_sn, nullptr, ln1g, ln1b, g_h1, SROWS);
        gridbar();
        dev_fused(g_q, g_fn, g_pupd, g_pmass, nullptr, 1, s_u);
        dev_gemm(g_h1, Wqkv, bqkv, nullptr, g_qkvb, SROWS, 3 * DD, DD, 0, s_u);
        gridbar();
        dev_reduce(g_pupd, g_pmass, g_ub);
        dev_blockattn(g_qkvb, g_ob, s_u);
        gridbar();
        dev_gemm(g_ub, Wv, nullptr, nullptr, g_upd, SROWS, DD, DD, 0, s_u);
        dev_gemm(g_ob, Wo, bo, g_sn, g_x1, SROWS, DD, DD, 0, s_u);
        gridbar();
        dev_ln(g_x1, nullptr, ln2g, ln2b, g_h2, SROWS);
        gridbar();
        dev_gemm(g_h2, W1, b1, nullptr, g_g1, SROWS, 4 * DD, DD, 1, s_u);
        gridbar();
        dev_gemm(g_g1, W2, b2, g_x1, g_x2, SROWS, DD, 4 * DD, 0, s_u);
        gridbar();
        dev_ln(g_upd, g_x2, mg, mb, g_h3, SROWS);
        gridbar();
        dev_gemm(g_h3, mW1, mb1, nullptr, g_g2, SROWS, 4 * DD, DD, 1, s_u);
        gridbar();
        dev_gemm(g_g2, mW2, mb2, g_slots, g_slots, SROWS, DD, 4 * DD, 0, s_u);
        gridbar();
    }

    dev_ln(g_slots, nullptr, ns_g, ns_b, g_sn, SROWS);
    gridbar();
    dev_gemm(g_sn, g_wqk, nullptr, nullptr, g_q, SROWS, DD, DD, 0, s_u);
    dev_copy(out, g_slots, SROWS * DD / 4);
    gridbar();
    dev_fused(g_q, g_fn, nullptr, nullptr, out + (size_t)SROWS * DD, 0, s_u);
}

// ---------------- host ----------------
extern "C" void kernel_launch(void* const* d_in, const int* in_sizes, int n_in,
                              void* d_out, int out_size) {
    const float* features  = (const float*)d_in[0];
    const float* slots_init= (const float*)d_in[1];
    const float* nf_g = (const float*)d_in[2];
    const float* nf_b = (const float*)d_in[3];
    const float* ns_g = (const float*)d_in[4];
    const float* ns_b = (const float*)d_in[5];
    const float* Wq   = (const float*)d_in[6];
    const float* Wk   = (const float*)d_in[7];
    const float* Wv   = (const float*)d_in[8];
    const float* mg   = (const float*)d_in[9];
    const float* mb   = (const float*)d_in[10];
    const float* mW1  = (const float*)d_in[11];
    const float* mb1  = (const float*)d_in[12];
    const float* mW2  = (const float*)d_in[13];
    const float* mb2  = (const float*)d_in[14];
    const float* b_ln1g = (const float*)d_in[15];
    const float* b_ln1b = (const float*)d_in[16];
    const float* b_Wqkv = (const float*)d_in[17];
    const float* b_bqkv = (const float*)d_in[18];
    const float* b_Wo   = (const float*)d_in[19];
    const float* b_bo   = (const float*)d_in[20];
    const float* b_ln2g = (const float*)d_in[21];
    const float* b_ln2b = (const float*)d_in[22];
    const float* b_W1   = (const float*)d_in[23];
    const float* b_b1   = (const float*)d_in[24];
    const float* b_W2   = (const float*)d_in[25];
    const float* b_b2   = (const float*)d_in[26];

    static int configured = 0;
    if (!configured) {
        cudaFuncSetAttribute(mega_kernel, cudaFuncAttributeMaxDynamicSharedMemorySize,
                             SMEM_BYTES);
        configured = 1;
    }

    mega_kernel<<<NB, NT, SMEM_BYTES>>>(features, slots_init, nf_g, nf_b, ns_g, ns_b,
                                        Wq, Wk, Wv, mg, mb, mW1, mb1, mW2, mb2,
                                        b_ln1g, b_ln1b, b_Wqkv, b_bqkv, b_Wo, b_bo,
                                        b_ln2g, b_ln2b, b_W1, b_b1, b_W2, b_b2,
                                        (float*)d_out);
}